// round 6
// baseline (speedup 1.0000x reference)
#include <cuda_runtime.h>
#include <math.h>

// ---------------- problem constants ----------------
#define O_   64
#define I_   64
#define KK   3
#define NH_  64
#define M_   32
#define B_   64
#define T_   8192
#define QD   320          // O*(K+2)
#define D_   (O_*I_*KK)   // 12288

// Scratch (allocation-free): effective conv weights in [i][k][o] layout + bias.
// [i][k][o] layout => consecutive o's contiguous => direct 64-bit packed weight pairs.
__device__ float g_weff[I_ * KK * O_];
__device__ float g_beff[O_];

__device__ __forceinline__ float siluf(float z) { return z / (1.0f + expf(-z)); }

// ---- packed f32x2 helpers (Blackwell FFMA2, PTX-only) ----
__device__ __forceinline__ unsigned long long pack2(float v) {
    unsigned long long r;
    asm("mov.b64 %0, {%1, %1};" : "=l"(r) : "f"(v));
    return r;
}
__device__ __forceinline__ void fma2(unsigned long long& d,
                                     unsigned long long a,
                                     unsigned long long b) {
    asm("fma.rn.f32x2 %0, %1, %2, %0;" : "+l"(d) : "l"(a), "l"(b));
}
__device__ __forceinline__ void unpack2(unsigned long long v, float& lo, float& hi) {
    asm("mov.b64 {%0, %1}, %2;" : "=f"(lo), "=f"(hi) : "l"(v));
}

// =====================================================================
// Prep kernel: entire q-pipeline -> effective weights. Single block.
// =====================================================================
__global__ void prep_kernel(
    const float* __restrict__ grads,  const float* __restrict__ q_ema,
    const float* __restrict__ W,      const float* __restrict__ conv_w,
    const float* __restrict__ conv_b, const float* __restrict__ ctrl_w,
    const float* __restrict__ ctrl_b, const float* __restrict__ cw_w,
    const float* __restrict__ cw_b,   const float* __restrict__ cb_w,
    const float* __restrict__ cb_b,   const float* __restrict__ cf_w,
    const float* __restrict__ cf_b,   const float* __restrict__ tau_w1,
    const float* __restrict__ tau_b1, const float* __restrict__ tau_w2,
    const float* __restrict__ tau_b2, const int*  __restrict__ trigger)
{
    __shared__ float s_rep[NH_ * O_];   // TRANSPOSED: s_rep[h*64 + o]
    __shared__ float s_q[QD];
    __shared__ float s_red[O_];
    __shared__ float s_sc[4];           // [0]=tau, [1..3]=top3 values
    __shared__ int   s_idx[3];
    __shared__ float s_g[64 * 49];      // padded tiles for the rep GEMM
    __shared__ float s_c[64 * 49];

    const int tid = threadIdx.x;  // 256 threads

    // ---- Phase 1: rep = silu( G(64x192) @ ctrl_w^T(192x64) + ctrl_b ) ----
    float acc[4][4];
    #pragma unroll
    for (int a = 0; a < 4; a++)
        #pragma unroll
        for (int b2 = 0; b2 < 4; b2++) acc[a][b2] = 0.0f;

    const int to = (tid & 15) * 4;   // o-tile base
    const int th = (tid >> 4) * 4;   // h-tile base

    for (int c = 0; c < 4; c++) {    // K chunks of 48
        for (int idx = tid; idx < 64 * 48; idx += 256) {
            int r = idx / 48, j = idx - r * 48;
            s_g[r * 49 + j] = grads[r * 192 + c * 48 + j];
            s_c[r * 49 + j] = ctrl_w[r * 192 + c * 48 + j];
        }
        __syncthreads();
        for (int j = 0; j < 48; j++) {
            float ga[4], ca[4];
            #pragma unroll
            for (int a = 0; a < 4; a++)  ga[a]  = s_g[(to + a) * 49 + j];
            #pragma unroll
            for (int b2 = 0; b2 < 4; b2++) ca[b2] = s_c[(th + b2) * 49 + j];
            #pragma unroll
            for (int a = 0; a < 4; a++)
                #pragma unroll
                for (int b2 = 0; b2 < 4; b2++)
                    acc[a][b2] = fmaf(ga[a], ca[b2], acc[a][b2]);
        }
        __syncthreads();
    }
    #pragma unroll
    for (int a = 0; a < 4; a++)
        #pragma unroll
        for (int b2 = 0; b2 < 4; b2++) {
            float z = acc[a][b2] + ctrl_b[th + b2];
            s_rep[(th + b2) * 64 + (to + a)] = siluf(z);  // transposed store
        }
    __syncthreads();

    // ---- Phase 2: per-o heads (w, b, f) and tau contribution ----
    if (tid < 64) {
        const int o = tid;
        float wv[3];
        #pragma unroll
        for (int k = 0; k < 3; k++) {
            float a = cw_b[k];
            for (int h = 0; h < 64; h++) a = fmaf(s_rep[h * 64 + o], cw_w[k * 64 + h], a);
            wv[k] = a;
        }
        float bv = cb_b[0], fv = cf_b[0];
        for (int h = 0; h < 64; h++) {
            float r = s_rep[h * 64 + o];
            bv = fmaf(r, cb_w[h], bv);
            fv = fmaf(r, cf_w[h], fv);
        }
        float t2 = tau_b2[0];
        for (int j = 0; j < 16; j++) {
            float z = tau_b1[j];
            for (int h = 0; h < 64; h++) z = fmaf(s_rep[h * 64 + o], tau_w1[j * 64 + h], z);
            t2 = fmaf(siluf(z), tau_w2[j], t2);
        }
        s_red[o] = 1.0f / (1.0f + expf(-t2));   // sigmoid
        s_q[o * 3 + 0] = wv[0];
        s_q[o * 3 + 1] = wv[1];
        s_q[o * 3 + 2] = wv[2];
        s_q[192 + o]   = bv;
        s_q[256 + o]   = fv;
    }
    __syncthreads();

    if (tid == 0) {
        float s = 0.0f;
        for (int o = 0; o < 64; o++) s += s_red[o];
        s_sc[0] = (s / 64.0f) * 0.5f + 0.5f;     // tau = mean(sigmoid)*0.5 + 0.5
    }
    __syncthreads();
    const float tau = s_sc[0];

    // ---- EMA mix: q = 0.5*q + 0.5*(0.3*q_ema + 0.7*q) ----
    for (int p = tid; p < QD; p += 256) {
        float qv = s_q[p];
        float qn = 0.3f * q_ema[p] + 0.7f * qv;
        s_q[p] = 0.5f * qv + 0.5f * qn;
    }
    __syncthreads();

    // ---- Trigger branch: softmax retrieval + top-3 mixing ----
    int trig_raw = trigger[0];
    bool trig = (trig_raw == 1) || (__int_as_float(trig_raw) == 1.0f);
    if (trig) {
        if (tid < 32) {
            float a = 0.0f;
            for (int p = 0; p < QD; p++) a = fmaf(s_q[p], W[p * 32 + tid], a);
            s_red[tid] = a * 2.0f;   // / TEMP (0.5)
        }
        __syncthreads();
        if (tid == 0) {
            float mx = -1e30f;
            for (int m = 0; m < 32; m++) mx = fmaxf(mx, s_red[m]);
            float ex[32]; float sum = 0.0f;
            for (int m = 0; m < 32; m++) { ex[m] = expf(s_red[m] - mx); sum += ex[m]; }
            unsigned used = 0u;
            for (int j = 0; j < 3; j++) {     // top-3, first-index tie-break (jax semantics)
                int best = 0; float bv2 = -1.0f;
                for (int m = 0; m < 32; m++)
                    if (!((used >> m) & 1u) && ex[m] > bv2) { bv2 = ex[m]; best = m; }
                used |= 1u << best;
                s_sc[1 + j] = bv2 / sum;      // att value
                s_idx[j] = best;
            }
        }
        __syncthreads();
        const float v0 = s_sc[1], v1 = s_sc[2], v2 = s_sc[3];
        const int   i0 = s_idx[0], i1 = s_idx[1], i2 = s_idx[2];
        for (int p = tid; p < QD; p += 256) {
            float oldq = W[p * 32 + i0] * v0 + W[p * 32 + i1] * v1 + W[p * 32 + i2] * v2;
            s_q[p] = tau * s_q[p] + (1.0f - tau) * oldq;
        }
        __syncthreads();
    }

    // ---- Fold into effective conv weights/bias ----
    // out = fq*(conv(x; conv_w*wq) + conv_b*bq)
    // Weff[i][k][o] = conv_w[o][i][k] * q[o*3+k] * q[256+o]
    for (int idx = tid; idx < D_; idx += 256) {
        int i = idx / 192;
        int r = idx - i * 192;
        int k = r / 64;
        int o = r - k * 64;
        g_weff[idx] = conv_w[(o * 64 + i) * 3 + k] * s_q[o * 3 + k] * s_q[256 + o];
    }
    if (tid < 64)
        g_beff[tid] = s_q[256 + tid] * conv_b[tid] * s_q[192 + tid];
}

// =====================================================================
// Conv kernel: out[b][o][t] = beff[o] + sum_{i,k} Weff[i][k][o]*x[b][i][t+k-1]
// Grid: (T/128, B). Block: 256 threads; thread tile = 8 o x 4 tokens,
// computed as 4 packed-f32x2 o-pairs x 4 tokens via fma.rn.f32x2.
// =====================================================================
__global__ __launch_bounds__(256)
void conv_kernel(const float* __restrict__ x, float* __restrict__ out)
{
    __shared__ float xs[I_ * 132];    // [i][130 tokens incl halo], padded to 132

    const int b  = blockIdx.y;
    const int t0 = blockIdx.x * 128;
    const int tid = threadIdx.x;

    const float* xb = x + (size_t)b * I_ * T_;
    for (int idx = tid; idx < I_ * 130; idx += 256) {
        int i = idx / 130;
        int p = idx - i * 130;
        int t = t0 - 1 + p;
        xs[i * 132 + p] = (t >= 0 && t < T_) ? xb[i * T_ + t] : 0.0f;
    }
    __syncthreads();

    const int og = (tid >> 5) * 8;    // 8 output channels per thread (warp-uniform)
    const int tb = (tid & 31) * 4;    // 4 tokens per thread

    // acc[op][j] = packed (out[og+2*op], out[og+2*op+1]) at token tb+j
    unsigned long long acc[4][4];
    #pragma unroll
    for (int op = 0; op < 4; op++)
        #pragma unroll
        for (int j = 0; j < 4; j++) acc[op][j] = 0ull;

    for (int i = 0; i < I_; i++) {
        // 6-token x window: covers taps k=0..2 for 4 outputs
        const float* xr = &xs[i * 132 + tb];
        float4 xa  = *(const float4*)xr;          // 16B aligned
        float2 xc  = *(const float2*)(xr + 4);
        unsigned long long xp[6];
        xp[0] = pack2(xa.x); xp[1] = pack2(xa.y); xp[2] = pack2(xa.z);
        xp[3] = pack2(xa.w); xp[4] = pack2(xc.x); xp[5] = pack2(xc.y);

        // Weights for this i: [k][o] rows, og..og+7 contiguous per k.
        // ulonglong2 load = 4 consecutive o's = 2 ready-packed (o,o+1) pairs.
        const ulonglong2* wp = (const ulonglong2*)(g_weff + i * 192 + og);
        #pragma unroll
        for (int k = 0; k < 3; k++) {
            ulonglong2 wa = wp[k * 16];       // (og+0,og+1),(og+2,og+3)
            ulonglong2 wb = wp[k * 16 + 1];   // (og+4,og+5),(og+6,og+7)
            #pragma unroll
            for (int j = 0; j < 4; j++) {
                fma2(acc[0][j], wa.x, xp[j + k]);
                fma2(acc[1][j], wa.y, xp[j + k]);
                fma2(acc[2][j], wb.x, xp[j + k]);
                fma2(acc[3][j], wb.y, xp[j + k]);
            }
        }
    }

    #pragma unroll
    for (int op = 0; op < 4; op++) {
        const int o0 = og + 2 * op;
        float lo[4], hi[4];
        #pragma unroll
        for (int j = 0; j < 4; j++) unpack2(acc[op][j], lo[j], hi[j]);
        float be0 = g_beff[o0];
        float be1 = g_beff[o0 + 1];
        float4 r0, r1;
        r0.x = lo[0] + be0; r0.y = lo[1] + be0; r0.z = lo[2] + be0; r0.w = lo[3] + be0;
        r1.x = hi[0] + be1; r1.y = hi[1] + be1; r1.z = hi[2] + be1; r1.w = hi[3] + be1;
        *(float4*)(out + ((size_t)(b * 64 + o0))     * T_ + t0 + tb) = r0;
        *(float4*)(out + ((size_t)(b * 64 + o0 + 1)) * T_ + t0 + tb) = r1;
    }
}

// =====================================================================
// Launch
// =====================================================================
extern "C" void kernel_launch(void* const* d_in, const int* in_sizes, int n_in,
                              void* d_out, int out_size)
{
    const float* x      = (const float*)d_in[0];
    const float* grads  = (const float*)d_in[1];
    const float* q_ema  = (const float*)d_in[2];
    const float* W      = (const float*)d_in[3];
    const float* conv_w = (const float*)d_in[4];
    const float* conv_b = (const float*)d_in[5];
    const float* ctrl_w = (const float*)d_in[6];
    const float* ctrl_b = (const float*)d_in[7];
    const float* cw_w   = (const float*)d_in[8];
    const float* cw_b   = (const float*)d_in[9];
    const float* cb_w   = (const float*)d_in[10];
    const float* cb_b   = (const float*)d_in[11];
    const float* cf_w   = (const float*)d_in[12];
    const float* cf_b   = (const float*)d_in[13];
    const float* tau_w1 = (const float*)d_in[14];
    const float* tau_b1 = (const float*)d_in[15];
    const float* tau_w2 = (const float*)d_in[16];
    const float* tau_b2 = (const float*)d_in[17];
    const int*   trigger= (const int*)  d_in[18];
    float* out = (float*)d_out;

    prep_kernel<<<1, 256>>>(grads, q_ema, W, conv_w, conv_b, ctrl_w, ctrl_b,
                            cw_w, cw_b, cb_w, cb_b, cf_w, cf_b,
                            tau_w1, tau_b1, tau_w2, tau_b2, trigger);

    conv_kernel<<<dim3(T_ / 128, B_), 256>>>(x, out);
}

// round 8
// speedup vs baseline: 1.3592x; 1.3592x over previous
#include <cuda_runtime.h>
#include <cuda_bf16.h>
#include <math.h>
#include <stdint.h>

// ---------------- problem constants ----------------
#define O_   64
#define I_   64
#define B_   64
#define T_   8192
#define QD   320          // O*(K+2)
#define MT   128          // tokens per tile (GEMM M)

// ---------------- device scratch (allocation-free) ----------------
// B operand: 6 matrices [(k*2+s)][o][i] bf16 (k = tap 0..2, s = 0 hi / 1 lo)
__device__ __align__(16) unsigned short g_bw[6 * 64 * 64];
__device__ float g_beff[64];

__device__ __forceinline__ float siluf(float z) { return z / (1.0f + expf(-z)); }

// ---------------- smem layout (dynamic, bytes) ----------------
#define ASTR     144                     // row stride (16B aligned, conflict-free LDSM)
#define OFF_AHI  0                       // 130 rows x 144
#define OFF_ALO  18720
#define OFF_B    37440                   // 384 rows x 144
#define OFF_BEFF 92736                   // 64 floats
#define SMEM_TOTAL 92992
// D stage reuses [0 .. 33792) = A region (dead after MMA passes)

static __device__ __forceinline__ uint32_t smem_u32(const void* p) {
    uint32_t a;
    asm("{ .reg .u64 t; cvta.to.shared.u64 t, %1; cvt.u32.u64 %0, t; }" : "=r"(a) : "l"(p));
    return a;
}

#define LDSM4(r0, r1, r2, r3, addr) \
    asm volatile("ldmatrix.sync.aligned.m8n8.x4.shared.b16 {%0,%1,%2,%3}, [%4];" \
                 : "=r"(r0), "=r"(r1), "=r"(r2), "=r"(r3) : "r"(addr))

#define MMA16816(C, A0, A1, A2, A3, B0, B1) \
    asm volatile("mma.sync.aligned.m16n8k16.row.col.f32.bf16.bf16.f32 " \
                 "{%0,%1,%2,%3}, {%4,%5,%6,%7}, {%8,%9}, {%0,%1,%2,%3};" \
                 : "+f"((C)[0]), "+f"((C)[1]), "+f"((C)[2]), "+f"((C)[3]) \
                 : "r"(A0), "r"(A1), "r"(A2), "r"(A3), "r"(B0), "r"(B1))

// =====================================================================
// Prep kernel: q-pipeline -> bf16-split effective weights. Single block.
// (numeric pipeline identical to the R5 kernel that passed at 5e-7)
// =====================================================================
__global__ void prep_kernel(
    const float* __restrict__ grads,  const float* __restrict__ q_ema,
    const float* __restrict__ W,      const float* __restrict__ conv_w,
    const float* __restrict__ conv_b, const float* __restrict__ ctrl_w,
    const float* __restrict__ ctrl_b, const float* __restrict__ cw_w,
    const float* __restrict__ cw_b,   const float* __restrict__ cb_w,
    const float* __restrict__ cb_b,   const float* __restrict__ cf_w,
    const float* __restrict__ cf_b,   const float* __restrict__ tau_w1,
    const float* __restrict__ tau_b1, const float* __restrict__ tau_w2,
    const float* __restrict__ tau_b2, const int*  __restrict__ trigger)
{
    __shared__ float s_rep[64 * 64];    // TRANSPOSED: s_rep[h*64 + o]
    __shared__ float s_q[QD];
    __shared__ float s_red[64];
    __shared__ float s_sc[4];
    __shared__ int   s_idx[3];
    __shared__ float s_g[64 * 49];
    __shared__ float s_c[64 * 49];

    const int tid = threadIdx.x;  // 256

    // ---- Phase 1: rep = silu( G(64x192) @ ctrl_w^T + ctrl_b ) ----
    float acc[4][4];
    #pragma unroll
    for (int a = 0; a < 4; a++)
        #pragma unroll
        for (int b2 = 0; b2 < 4; b2++) acc[a][b2] = 0.0f;

    const int to = (tid & 15) * 4;
    const int th = (tid >> 4) * 4;

    for (int c = 0; c < 4; c++) {
        for (int idx = tid; idx < 64 * 48; idx += 256) {
            int r = idx / 48, j = idx - r * 48;
            s_g[r * 49 + j] = grads[r * 192 + c * 48 + j];
            s_c[r * 49 + j] = ctrl_w[r * 192 + c * 48 + j];
        }
        __syncthreads();
        for (int j = 0; j < 48; j++) {
            float ga[4], ca[4];
            #pragma unroll
            for (int a = 0; a < 4; a++)  ga[a]  = s_g[(to + a) * 49 + j];
            #pragma unroll
            for (int b2 = 0; b2 < 4; b2++) ca[b2] = s_c[(th + b2) * 49 + j];
            #pragma unroll
            for (int a = 0; a < 4; a++)
                #pragma unroll
                for (int b2 = 0; b2 < 4; b2++)
                    acc[a][b2] = fmaf(ga[a], ca[b2], acc[a][b2]);
        }
        __syncthreads();
    }
    #pragma unroll
    for (int a = 0; a < 4; a++)
        #pragma unroll
        for (int b2 = 0; b2 < 4; b2++) {
            float z = acc[a][b2] + ctrl_b[th + b2];
            s_rep[(th + b2) * 64 + (to + a)] = siluf(z);
        }
    __syncthreads();

    // ---- Phase 2: heads + tau ----
    if (tid < 64) {
        const int o = tid;
        float wv[3];
        #pragma unroll
        for (int k = 0; k < 3; k++) {
            float a = cw_b[k];
            for (int h = 0; h < 64; h++) a = fmaf(s_rep[h * 64 + o], cw_w[k * 64 + h], a);
            wv[k] = a;
        }
        float bv = cb_b[0], fv = cf_b[0];
        for (int h = 0; h < 64; h++) {
            float r = s_rep[h * 64 + o];
            bv = fmaf(r, cb_w[h], bv);
            fv = fmaf(r, cf_w[h], fv);
        }
        float t2 = tau_b2[0];
        for (int j = 0; j < 16; j++) {
            float z = tau_b1[j];
            for (int h = 0; h < 64; h++) z = fmaf(s_rep[h * 64 + o], tau_w1[j * 64 + h], z);
            t2 = fmaf(siluf(z), tau_w2[j], t2);
        }
        s_red[o] = 1.0f / (1.0f + expf(-t2));
        s_q[o * 3 + 0] = wv[0];
        s_q[o * 3 + 1] = wv[1];
        s_q[o * 3 + 2] = wv[2];
        s_q[192 + o]   = bv;
        s_q[256 + o]   = fv;
    }
    __syncthreads();

    if (tid == 0) {
        float s = 0.0f;
        for (int o = 0; o < 64; o++) s += s_red[o];
        s_sc[0] = (s / 64.0f) * 0.5f + 0.5f;
    }
    __syncthreads();
    const float tau = s_sc[0];

    // ---- EMA mix ----
    for (int p = tid; p < QD; p += 256) {
        float qv = s_q[p];
        float qn = 0.3f * q_ema[p] + 0.7f * qv;
        s_q[p] = 0.5f * qv + 0.5f * qn;
    }
    __syncthreads();

    // ---- Trigger: softmax retrieval + top-3 ----
    int trig_raw = trigger[0];
    bool trig = (trig_raw == 1) || (__int_as_float(trig_raw) == 1.0f);
    if (trig) {
        if (tid < 32) {
            float a = 0.0f;
            for (int p = 0; p < QD; p++) a = fmaf(s_q[p], W[p * 32 + tid], a);
            s_red[tid] = a * 2.0f;
        }
        __syncthreads();
        if (tid == 0) {
            float mx = -1e30f;
            for (int m = 0; m < 32; m++) mx = fmaxf(mx, s_red[m]);
            float ex[32]; float sum = 0.0f;
            for (int m = 0; m < 32; m++) { ex[m] = expf(s_red[m] - mx); sum += ex[m]; }
            unsigned used = 0u;
            for (int j = 0; j < 3; j++) {
                int best = 0; float bv2 = -1.0f;
                for (int m = 0; m < 32; m++)
                    if (!((used >> m) & 1u) && ex[m] > bv2) { bv2 = ex[m]; best = m; }
                used |= 1u << best;
                s_sc[1 + j] = bv2 / sum;
                s_idx[j] = best;
            }
        }
        __syncthreads();
        const float v0 = s_sc[1], v1 = s_sc[2], v2 = s_sc[3];
        const int   i0 = s_idx[0], i1 = s_idx[1], i2 = s_idx[2];
        for (int p = tid; p < QD; p += 256) {
            float oldq = W[p * 32 + i0] * v0 + W[p * 32 + i1] * v1 + W[p * 32 + i2] * v2;
            s_q[p] = tau * s_q[p] + (1.0f - tau) * oldq;
        }
        __syncthreads();
    }

    // ---- Fold into bf16-split B matrices: g_bw[(k*2+s)][o][i] ----
    for (int idx = tid; idx < 6 * 4096; idx += 256) {
        int m = idx >> 12;          // 0..5
        int r = idx & 4095;
        int o = r >> 6, i = r & 63;
        int k = m >> 1, s = m & 1;
        float wv = conv_w[(o * 64 + i) * 3 + k] * s_q[o * 3 + k] * s_q[256 + o];
        __nv_bfloat16 h = __float2bfloat16(wv);
        unsigned short v;
        if (s == 0) v = __bfloat16_as_ushort(h);
        else        v = __bfloat16_as_ushort(__float2bfloat16(wv - __bfloat162float(h)));
        g_bw[idx] = v;
    }
    if (tid < 64)
        g_beff[tid] = s_q[256 + tid] * conv_b[tid] * s_q[192 + tid];
}

// =====================================================================
// Conv as 3 shifted GEMMs via mma.sync bf16 (2-term split, 9 passes K=64).
// Grid (T/128, B) = (64, 64). 256 threads (8 warps: 4 m-tiles x 2 n-tiles).
// =====================================================================
__global__ void __launch_bounds__(256, 2)
conv_mma_kernel(const float* __restrict__ x, float* __restrict__ out)
{
    extern __shared__ char smem[];
    const int tid  = threadIdx.x;
    const int lane = tid & 31;
    const int wid  = tid >> 5;
    const int b    = blockIdx.y;
    const int t0   = blockIdx.x * MT;

    // ---- load B matrices (6 x 64 rows x 128B) into 144B-stride rows ----
    {
        const uint4* src = (const uint4*)g_bw;          // 8 x 16B chunks per row
        for (int idx = tid; idx < 384 * 8; idx += 256) {
            int row = idx >> 3, c = idx & 7;
            *(uint4*)(smem + OFF_B + row * ASTR + c * 16) = src[idx];
        }
    }
    if (tid < 64) *(float*)(smem + OFF_BEFF + tid * 4) = g_beff[tid];

    // ---- im2col: A_hi/A_lo [row p][i], p = 0..129 <-> token t0-1+p ----
    const float* xb = x + (size_t)b * I_ * T_;
    for (int idx = tid; idx < 130 * 64; idx += 256) {
        int i = idx / 130;
        int p = idx - i * 130;
        int t = t0 - 1 + p;
        float v = (t >= 0 && t < T_) ? __ldg(xb + (size_t)i * T_ + t) : 0.0f;
        __nv_bfloat16 h = __float2bfloat16(v);
        __nv_bfloat16 l = __float2bfloat16(v - __bfloat162float(h));
        *(unsigned short*)(smem + OFF_AHI + p * ASTR + i * 2) = __bfloat16_as_ushort(h);
        *(unsigned short*)(smem + OFF_ALO + p * ASTR + i * 2) = __bfloat16_as_ushort(l);
    }
    __syncthreads();

    // ---- warp tiling: 32 (m) x 32 (n) per warp ----
    const int R0 = (wid & 3) * 32;      // token-row base
    const int n0 = (wid >> 2) * 32;     // output-channel base

    // ldmatrix lane address offsets (bytes within a matrix region)
    const int aoff = (lane & 15) * ASTR + (lane >> 4) * 16;
    const int boff = ((lane & 7) + ((lane >> 4) << 3)) * ASTR + ((lane >> 3) & 1) * 16;

    float c[2][4][4];
    #pragma unroll
    for (int mi = 0; mi < 2; mi++)
        #pragma unroll
        for (int j = 0; j < 4; j++)
            #pragma unroll
            for (int r = 0; r < 4; r++) c[mi][j][r] = 0.0f;

    const uint32_t sb = smem_u32(smem);

    // 9 passes: term 0 = Ah*Bh, 1 = Ah*Bl, 2 = Al*Bh; each over taps 0..2
    #pragma unroll 1
    for (int pass = 0; pass < 9; pass++) {
        const int term  = pass / 3;
        const int shift = pass - term * 3;
        const uint32_t abase = sb + (term == 2 ? OFF_ALO : OFF_AHI)
                             + (uint32_t)(R0 + shift) * ASTR + aoff;
        const int bm = shift * 2 + (term == 1 ? 1 : 0);
        const uint32_t bbase = sb + OFF_B + (uint32_t)(bm * 64 + n0) * ASTR + boff;

        #pragma unroll
        for (int kk = 0; kk < 4; kk++) {
            uint32_t a0, a1, a2, a3, a4, a5, a6, a7;
            uint32_t b0, b1, b2, b3, b4, b5, b6, b7;
            LDSM4(a0, a1, a2, a3, abase + kk * 32);
            LDSM4(a4, a5, a6, a7, abase + 16 * ASTR + kk * 32);
            LDSM4(b0, b1, b2, b3, bbase + kk * 32);
            LDSM4(b4, b5, b6, b7, bbase + 16 * ASTR + kk * 32);

            MMA16816(c[0][0], a0, a1, a2, a3, b0, b1);
            MMA16816(c[0][1], a0, a1, a2, a3, b2, b3);
            MMA16816(c[0][2], a0, a1, a2, a3, b4, b5);
            MMA16816(c[0][3], a0, a1, a2, a3, b6, b7);
            MMA16816(c[1][0], a4, a5, a6, a7, b0, b1);
            MMA16816(c[1][1], a4, a5, a6, a7, b2, b3);
            MMA16816(c[1][2], a4, a5, a6, a7, b4, b5);
            MMA16816(c[1][3], a4, a5, a6, a7, b6, b7);
        }
    }
    __syncthreads();   // A region dead -> reuse as D stage

    // ---- stage D[o][t] (row stride 132 floats; conflict-free) ----
    {
        float* sD = (float*)smem;
        const int trow = lane >> 2;
        const int tcol = (lane & 3) * 2;
        #pragma unroll
        for (int mi = 0; mi < 2; mi++)
            #pragma unroll
            for (int j = 0; j < 4; j++) {
                const int o  = n0 + j * 8 + tcol;
                const int tt = R0 + mi * 16 + trow;
                sD[o * 132 + tt]           = c[mi][j][0];
                sD[(o + 1) * 132 + tt]     = c[mi][j][1];
                sD[o * 132 + tt + 8]       = c[mi][j][2];
                sD[(o + 1) * 132 + tt + 8] = c[mi][j][3];
            }
    }
    __syncthreads();

    // ---- coalesced epilogue: out[b][o][t0..t0+127] ----
    {
        const float* sD = (const float*)smem;
        const float* be = (const float*)(smem + OFF_BEFF);
        for (int idx = tid; idx < 2048; idx += 256) {
            int o  = idx >> 5;
            int tc = (idx & 31) * 4;
            float4 v = *(const float4*)(sD + o * 132 + tc);
            float beo = be[o];
            v.x += beo; v.y += beo; v.z += beo; v.w += beo;
            *(float4*)(out + ((size_t)(b * 64 + o)) * T_ + t0 + tc) = v;
        }
    }
}

// =====================================================================
// Launch
// =====================================================================
extern "C" void kernel_launch(void* const* d_in, const int* in_sizes, int n_in,
                              void* d_out, int out_size)
{
    const float* x      = (const float*)d_in[0];
    const float* grads  = (const float*)d_in[1];
    const float* q_ema  = (const float*)d_in[2];
    const float* W      = (const float*)d_in[3];
    const float* conv_w = (const float*)d_in[4];
    const float* conv_b = (const float*)d_in[5];
    const float* ctrl_w = (const float*)d_in[6];
    const float* ctrl_b = (const float*)d_in[7];
    const float* cw_w   = (const float*)d_in[8];
    const float* cw_b   = (const float*)d_in[9];
    const float* cb_w   = (const float*)d_in[10];
    const float* cb_b   = (const float*)d_in[11];
    const float* cf_w   = (const float*)d_in[12];
    const float* cf_b   = (const float*)d_in[13];
    const float* tau_w1 = (const float*)d_in[14];
    const float* tau_b1 = (const float*)d_in[15];
    const float* tau_w2 = (const float*)d_in[16];
    const float* tau_b2 = (const float*)d_in[17];
    const int*   trigger= (const int*)  d_in[18];
    float* out = (float*)d_out;

    cudaFuncSetAttribute(conv_mma_kernel,
                         cudaFuncAttributeMaxDynamicSharedMemorySize, SMEM_TOTAL);

    prep_kernel<<<1, 256>>>(grads, q_ema, W, conv_w, conv_b, ctrl_w, ctrl_b,
                            cw_w, cw_b, cb_w, cb_b, cf_w, cf_b,
                            tau_w1, tau_b1, tau_w2, tau_b2, trigger);

    conv_mma_kernel<<<dim3(T_ / MT, B_), 256, SMEM_TOTAL>>>(x, out);
}